// round 11
// baseline (speedup 1.0000x reference)
#include <cuda_runtime.h>
#include <cuda_fp16.h>

#define DIMC 128
#define HEADS 8
#define HD 16
#define HH 32
#define WW 32
#define ZZ 8
#define NPTS 8192   // 32*32*8
#define NXV 1024    // 16*16*4

typedef unsigned long long u64;

// Scratch (device globals)
__device__ float   g_stats_x[DIMC * 2];
__device__ float   g_stats_s[DIMC * 2];
__device__ __half2 g_q16[HEADS * NXV * 8];     // [head][m][8 half2]
__device__ __half2 g_k16[HEADS * NPTS * 8];    // [head][n][8 half2]
__device__ __half2 g_v16[HEADS * NPTS * 8];    // [head][n][8 half2]
__device__ __half  g_o16[NPTS * DIMC];         // [n][j] row-major attn output

// ---- packed f32x2 helpers -------------------------------------------------
__device__ __forceinline__ u64 pk2(float x) {
    u64 r; unsigned xi = __float_as_uint(x);
    asm("mov.b64 %0,{%1,%1};" : "=l"(r) : "r"(xi));
    return r;
}
__device__ __forceinline__ void ffma2(u64& d, u64 a, u64 b) {
    asm("fma.rn.f32x2 %0,%1,%2,%0;" : "+l"(d) : "l"(a), "l"(b));
}
__device__ __forceinline__ float2 up2(u64 v) {
    unsigned lo, hi;
    asm("mov.b64 {%0,%1},%2;" : "=r"(lo), "=r"(hi) : "l"(v));
    return make_float2(__uint_as_float(lo), __uint_as_float(hi));
}

// ---------------------------------------------------------------------------
// Kernel 1: instance-norm statistics
// ---------------------------------------------------------------------------
__global__ void stats_kernel(const float* __restrict__ x,
                             const float* __restrict__ skip) {
    int c = blockIdx.x;
    const float* src; int n; float* dst;
    if (c < DIMC) { src = x + c * NXV;              n = NXV;  dst = g_stats_x + c * 2; }
    else          { src = skip + (c - DIMC) * NPTS; n = NPTS; dst = g_stats_s + (c - DIMC) * 2; }

    float s = 0.f, s2 = 0.f;
    for (int i = threadIdx.x; i < n; i += 256) {
        float v = src[i];
        s += v; s2 += v * v;
    }
    __shared__ float sh1[8], sh2[8];
    #pragma unroll
    for (int o = 16; o; o >>= 1) {
        s  += __shfl_down_sync(0xffffffffu, s,  o);
        s2 += __shfl_down_sync(0xffffffffu, s2, o);
    }
    int wid = threadIdx.x >> 5, lid = threadIdx.x & 31;
    if (lid == 0) { sh1[wid] = s; sh2[wid] = s2; }
    __syncthreads();
    if (threadIdx.x == 0) {
        float ts = 0.f, ts2 = 0.f;
        #pragma unroll
        for (int i = 0; i < 8; i++) { ts += sh1[i]; ts2 += sh2[i]; }
        float mean = ts / n;
        float var  = ts2 / n - mean * mean;
        dst[0] = mean;
        dst[1] = rsqrtf(var + 1e-5f);
    }
}

// ---- mma.sync m16n8k16 fp16 -> fp32 ---------------------------------------
__device__ __forceinline__ void mma16816(float* d, unsigned a0, unsigned a1,
                                         unsigned a2, unsigned a3,
                                         unsigned b0, unsigned b1) {
    asm volatile(
        "mma.sync.aligned.m16n8k16.row.col.f32.f16.f16.f32 "
        "{%0,%1,%2,%3},{%4,%5,%6,%7},{%8,%9},{%0,%1,%2,%3};"
        : "+f"(d[0]), "+f"(d[1]), "+f"(d[2]), "+f"(d[3])
        : "r"(a0), "r"(a1), "r"(a2), "r"(a3), "r"(b0), "r"(b1));
}

#define SSTR 136   // smem row stride (halves)

// ---------------------------------------------------------------------------
// Kernel 2: fused Q/K/V projection via tensor cores. grid 272:
//   blocks [0,128): K   [128,256): V   [256,272): Q
// One 64n x 128j x 128c tile per block (halved vs R9 for latency overlap).
// 8 warps = 4 m16-groups x 2 j-halves (64 j each), 8 n8-tiles per warp.
// ---------------------------------------------------------------------------
__global__ __launch_bounds__(256) void qkv_mma(
        const float* __restrict__ x,  const float* __restrict__ skip,
        const float* __restrict__ Wq, const float* __restrict__ bq,
        const float* __restrict__ Wk, const float* __restrict__ bk,
        const float* __restrict__ Wv, const float* __restrict__ bv) {
    extern __shared__ __half shm[];
    __half (*sA)[SSTR] = (__half(*)[SSTR])shm;                 // [64 n][128 c]
    __half (*sB)[SSTR] = (__half(*)[SSTR])(shm + 64 * SSTR);   // [128 j][128 c]

    int bid = blockIdx.x;
    const float *src, *Wt, *bt, *stats;
    __half2* outp; int strideN; float scale; int n0;
    if (bid < 128) {
        src = skip; Wt = Wk; bt = bk; stats = g_stats_s;
        outp = g_k16; strideN = NPTS; scale = 1.f; n0 = bid * 64;
    } else if (bid < 256) {
        src = skip; Wt = Wv; bt = bv; stats = g_stats_s;
        outp = g_v16; strideN = NPTS; scale = 1.f; n0 = (bid - 128) * 64;
    } else {
        src = x; Wt = Wq; bt = bq; stats = g_stats_x;
        outp = g_q16; strideN = NXV; scale = 0.25f; n0 = (bid - 256) * 64;
    }
    int tid = threadIdx.x;

    {
        int c = tid & 127, hf = tid >> 7;
        float mu = stats[c * 2], rs = stats[c * 2 + 1];
        // Stage A: normalize + transpose [c][n] -> [n][c], 32 rows per half
        const float* sp = src + c * strideN + n0 + hf * 32;
        #pragma unroll
        for (int i = 0; i < 8; i++) {
            float4 v = *(const float4*)(sp + i * 4);
            int n = hf * 32 + i * 4;
            sA[n + 0][c] = __float2half((v.x - mu) * rs);
            sA[n + 1][c] = __float2half((v.y - mu) * rs);
            sA[n + 2][c] = __float2half((v.z - mu) * rs);
            sA[n + 3][c] = __float2half((v.w - mu) * rs);
        }
        // Stage B: transpose W [c][j] -> [j][c], 64 j per half
        const float* wp = Wt + c * DIMC + hf * 64;
        #pragma unroll
        for (int i = 0; i < 16; i++) {
            float4 v = *(const float4*)(wp + i * 4);
            int j = hf * 64 + i * 4;
            sB[j + 0][c] = __float2half(v.x);
            sB[j + 1][c] = __float2half(v.y);
            sB[j + 2][c] = __float2half(v.z);
            sB[j + 3][c] = __float2half(v.w);
        }
    }
    __syncthreads();

    int w = tid >> 5, t = tid & 31;
    int g = t >> 2, i2 = (t & 3) * 2;
    int mg = w & 3, jh = w >> 2;
    int mrow = mg * 16;

    float acc[8][4];
    #pragma unroll
    for (int nt = 0; nt < 8; nt++)
        #pragma unroll
        for (int p = 0; p < 4; p++) acc[nt][p] = 0.f;

    #pragma unroll
    for (int kc = 0; kc < 8; kc++) {
        int k0 = kc * 16;
        unsigned a0 = *(const unsigned*)&sA[mrow + g][k0 + i2];
        unsigned a1 = *(const unsigned*)&sA[mrow + g + 8][k0 + i2];
        unsigned a2 = *(const unsigned*)&sA[mrow + g][k0 + i2 + 8];
        unsigned a3 = *(const unsigned*)&sA[mrow + g + 8][k0 + i2 + 8];
        #pragma unroll
        for (int nt = 0; nt < 8; nt++) {
            unsigned b0 = *(const unsigned*)&sB[jh * 64 + nt * 8 + g][k0 + i2];
            unsigned b1 = *(const unsigned*)&sB[jh * 64 + nt * 8 + g][k0 + i2 + 8];
            mma16816(acc[nt], a0, a1, a2, a3, b0, b1);
        }
    }

    int n1 = n0 + mrow + g;
    #pragma unroll
    for (int nt = 0; nt < 8; nt++) {
        int j = jh * 64 + nt * 8 + i2;
        float2 bb = *(const float2*)&bt[j];
        int head = j >> 4;
        int jj = (j & 15) >> 1;
        outp[(head * strideN + n1) * 8 + jj] =
            __floats2half2_rn((acc[nt][0] + bb.x) * scale,
                              (acc[nt][1] + bb.y) * scale);
        outp[(head * strideN + n1 + 8) * 8 + jj] =
            __floats2half2_rn((acc[nt][2] + bb.x) * scale,
                              (acc[nt][3] + bb.y) * scale);
    }
}

// ---------------------------------------------------------------------------
// Kernel 3: neighborhood attention, z-pair threads.
// Tile 8(h) x 8(w) x 8(z) = 512 points, 256 threads, 2 z-points per thread
// (they share the SAME q vector; their 5-windows overlap in >=4 positions,
// so each K-dot / V-load serves ~2 contributions).
// Halo 12x12x8 = 1152 pos of fp16 k/v, swizzled smem (~77KB).
// grid (4 hb, 4 wb, 8 heads) = 128 blocks -> single balanced wave.
// No-max softmax (logits O(0.1)), fp32 accumulators via f32x2 FFMA.
// ---------------------------------------------------------------------------
#define WHALO 12
__global__ __launch_bounds__(256) void attn_kernel(const float* __restrict__ rpb) {
    extern __shared__ float smem[];
    float4* sk4 = (float4*)smem;              // 2304 float4 (1152 pos * 2)
    float4* sv4 = sk4 + 2304;                 // 2304 float4
    float*  sb  = (float*)(sv4 + 2304);       // 729 bias

    int head = blockIdx.z;
    int h0 = blockIdx.x * 8, w0 = blockIdx.y * 8;
    int hlo = min(max(h0 - 2, 0), HH - 5);
    int wlo = min(max(w0 - 2, 0), WW - 5);
    int tid = threadIdx.x;

    for (int i = tid; i < 729; i += 256) sb[i] = rpb[head * 729 + i];

    const float4* gk4 = (const float4*)g_k16 + head * (NPTS * 2);
    const float4* gv4 = (const float4*)g_v16 + head * (NPTS * 2);
    #pragma unroll
    for (int it = 0; it < 9; it++) {
        int idx = it * 256 + tid;             // 2304 (pos,d4) pairs
        int d4 = idx & 1, pos = idx >> 1;
        int col = pos >> 3, z1 = pos & 7;
        int wh = col / WHALO, wwi = col - wh * WHALO;
        int gh = min(hlo + wh, HH - 1);
        int gw = min(wlo + wwi, WW - 1);
        int n = gh * 256 + gw * 8 + z1;
        // swizzle: permute z-slot by col&3, f4-half by col&1
        int ph = col * 16 + ((z1 ^ (col & 3)) << 1) + (d4 ^ (col & 1));
        sk4[ph] = gk4[n * 2 + d4];
        sv4[ph] = gv4[n * 2 + d4];
    }
    __syncthreads();

    int zg = tid & 3, dw = (tid >> 2) & 7, dh = tid >> 5;
    int z0 = zg * 2;
    int h = h0 + dh, w = w0 + dw;
    int sh = min(max(h - 2, 0), HH - 5);
    int sw = min(max(w - 2, 0), WW - 5);
    int sz0 = min(max(z0 - 2, 0), ZZ - 5);
    int sz1 = min(max(z0 - 1, 0), ZZ - 5);
    int d = sz1 - sz0;            // 0 or 1
    int cnt = 5 + d;              // distinct z-positions covering both windows
    int m = (h >> 1) * 64 + (w >> 1) * 4 + zg;   // shared parent voxel

    __half2 q2[8];
    {
        const float4* gq4 = (const float4*)g_q16 + (head * NXV + m) * 2;
        float4 qA = gq4[0], qB = gq4[1];
        const __half2* qa = (const __half2*)&qA;
        const __half2* qb = (const __half2*)&qB;
        #pragma unroll
        for (int i = 0; i < 4; i++) { q2[i] = qa[i]; q2[4 + i] = qb[i]; }
    }

    int bh = sh - h + 4, bw = sw - w + 4;
    int bz0 = sz0 - z0 + 4;       // point1's bias index is exactly -1 of point0's

    float sum0 = 0.f, sum1 = 0.f;
    u64 acc0[8], acc1[8];
    #pragma unroll
    for (int i = 0; i < 8; i++) { acc0[i] = 0ull; acc1[i] = 0ull; }

    for (int jh = 0; jh < 5; jh++) {
        int colh = (sh + jh - hlo) * WHALO;
        const float* bph = sb + (bh + jh) * 81 + bz0;
        for (int jw = 0; jw < 5; jw++) {
            int col = colh + (sw + jw - wlo);
            int m3c = col & 3, e = col & 1;
            int cb = col * 16;
            const float* bp = bph + (bw + jw) * 9;
            #pragma unroll 6
            for (int u = 0; u < cnt; u++) {
                int zz = sz0 + u;
                int ph = cb + ((zz ^ m3c) << 1);
                float4 kA = sk4[ph + e];
                float4 kB = sk4[ph + (1 ^ e)];
                const __half2* ka = (const __half2*)&kA;
                const __half2* kb = (const __half2*)&kB;
                __half2 t0 = __hmul2(q2[0], ka[0]);
                __half2 t1 = __hmul2(q2[1], ka[1]);
                t0 = __hfma2(q2[2], ka[2], t0);
                t1 = __hfma2(q2[3], ka[3], t1);
                t0 = __hfma2(q2[4], kb[0], t0);
                t1 = __hfma2(q2[5], kb[1], t1);
                t0 = __hfma2(q2[6], kb[2], t0);
                t1 = __hfma2(q2[7], kb[3], t1);
                float2 lf = __half22float2(__hadd2(t0, t1));
                float dotv = lf.x + lf.y;

                float4 vA = sv4[ph + e];
                float4 vB = sv4[ph + (1 ^ e)];
                const __half2* va = (const __half2*)&vA;
                const __half2* vb = (const __half2*)&vB;
                float2 vf[8];
                #pragma unroll
                for (int i = 0; i < 4; i++) {
                    vf[i]     = __half22float2(va[i]);
                    vf[4 + i] = __half22float2(vb[i]);
                }
                if (u <= 4) {                       // point0 window
                    float p = __expf(bp[u] + dotv);
                    sum0 += p;
                    u64 pp = pk2(p);
                    #pragma unroll
                    for (int i = 0; i < 8; i++)
                        ffma2(acc0[i], pp, *(const u64*)&vf[i]);
                }
                if (u >= d) {                       // point1 window
                    float p = __expf(bp[u - 1] + dotv);
                    sum1 += p;
                    u64 pp = pk2(p);
                    #pragma unroll
                    for (int i = 0; i < 8; i++)
                        ffma2(acc1[i], pp, *(const u64*)&vf[i]);
                }
            }
        }
    }

    int n = h * 256 + w * 8 + z0;
    {
        float inv = 1.f / sum0;
        __half2 o2[8];
        #pragma unroll
        for (int i = 0; i < 8; i++) {
            float2 f = up2(acc0[i]);
            o2[i] = __floats2half2_rn(f.x * inv, f.y * inv);
        }
        float4* dst = (float4*)(g_o16 + n * DIMC + head * 16);
        dst[0] = ((const float4*)o2)[0];
        dst[1] = ((const float4*)o2)[1];
    }
    {
        float inv = 1.f / sum1;
        __half2 o2[8];
        #pragma unroll
        for (int i = 0; i < 8; i++) {
            float2 f = up2(acc1[i]);
            o2[i] = __floats2half2_rn(f.x * inv, f.y * inv);
        }
        float4* dst = (float4*)(g_o16 + (n + 1) * DIMC + head * 16);
        dst[0] = ((const float4*)o2)[0];
        dst[1] = ((const float4*)o2)[1];
    }
}

// ---------------------------------------------------------------------------
// Kernel 4: output projection via tensor cores. grid 256 =
// (128 n-tiles) x (2 c-halves). Tile 64n x 64c x 128k.
// 8 warps = 4 m16-groups x 2 c-halves (32 c each -> 4 n8-tiles/warp).
// ---------------------------------------------------------------------------
__global__ __launch_bounds__(256) void proj_mma(
        const float* __restrict__ Wo, const float* __restrict__ bo,
        float* __restrict__ outp) {
    extern __shared__ __half shm[];
    __half (*sA)[SSTR] = (__half(*)[SSTR])shm;                 // [64 n][128 j]
    __half (*sB)[SSTR] = (__half(*)[SSTR])(shm + 64 * SSTR);   // [64 c][128 j]

    int n0 = (blockIdx.x >> 1) * 64;
    int c0 = (blockIdx.x & 1) * 64;
    int tid = threadIdx.x;

    // Stage A: copy fp16 [n][j]
    {
        int n = tid & 63, jh3 = (tid >> 6) * 32;
        const float4* gA = (const float4*)(g_o16 + (n0 + n) * DIMC + jh3);
        float4* dA = (float4*)&sA[n][jh3];
        #pragma unroll
        for (int i = 0; i < 4; i++) dA[i] = gA[i];
    }
    // Stage B: transpose Wo [j][c] -> [c][j] fp16
    {
        int k = tid & 127, chh = (tid >> 7) * 32;
        const float* wp = Wo + k * DIMC + c0 + chh;
        #pragma unroll
        for (int i = 0; i < 8; i++) {
            float4 v = *(const float4*)(wp + i * 4);
            int cc = chh + i * 4;
            sB[cc + 0][k] = __float2half(v.x);
            sB[cc + 1][k] = __float2half(v.y);
            sB[cc + 2][k] = __float2half(v.z);
            sB[cc + 3][k] = __float2half(v.w);
        }
    }
    __syncthreads();

    int w = tid >> 5, t = tid & 31;
    int g = t >> 2, i2 = (t & 3) * 2;
    int mg = w & 3, ch = w >> 2;
    int mrow = mg * 16;

    float acc[4][4];
    #pragma unroll
    for (int nt = 0; nt < 4; nt++)
        #pragma unroll
        for (int p = 0; p < 4; p++) acc[nt][p] = 0.f;

    #pragma unroll
    for (int kc = 0; kc < 8; kc++) {
        int k0 = kc * 16;
        unsigned a0 = *(const unsigned*)&sA[mrow + g][k0 + i2];
        unsigned a1 = *(const unsigned*)&sA[mrow + g + 8][k0 + i2];
        unsigned a2 = *(const unsigned*)&sA[mrow + g][k0 + i2 + 8];
        unsigned a3 = *(const unsigned*)&sA[mrow + g + 8][k0 + i2 + 8];
        #pragma unroll
        for (int nt = 0; nt < 4; nt++) {
            unsigned b0 = *(const unsigned*)&sB[ch * 32 + nt * 8 + g][k0 + i2];
            unsigned b1 = *(const unsigned*)&sB[ch * 32 + nt * 8 + g][k0 + i2 + 8];
            mma16816(acc[nt], a0, a1, a2, a3, b0, b1);
        }
    }

    int n1 = n0 + mrow + g;
    #pragma unroll
    for (int nt = 0; nt < 4; nt++) {
        int c = c0 + ch * 32 + nt * 8 + i2;
        float2 bb = *(const float2*)&bo[c];
        outp[c * NPTS + n1]           = acc[nt][0] + bb.x;
        outp[(c + 1) * NPTS + n1]     = acc[nt][1] + bb.y;
        outp[c * NPTS + n1 + 8]       = acc[nt][2] + bb.x;
        outp[(c + 1) * NPTS + n1 + 8] = acc[nt][3] + bb.y;
    }
}

// ---------------------------------------------------------------------------
extern "C" void kernel_launch(void* const* d_in, const int* in_sizes, int n_in,
                              void* d_out, int out_size) {
    const float* x    = (const float*)d_in[0];
    const float* skip = (const float*)d_in[1];
    const float* Wq   = (const float*)d_in[2];
    const float* bq   = (const float*)d_in[3];
    const float* Wk   = (const float*)d_in[4];
    const float* bk   = (const float*)d_in[5];
    const float* Wv   = (const float*)d_in[6];
    const float* bv   = (const float*)d_in[7];
    const float* rpb  = (const float*)d_in[8];
    const float* Wo   = (const float*)d_in[9];
    const float* bo   = (const float*)d_in[10];
    float* outp = (float*)d_out;

    const int attn_smem = (2304 + 2304) * 16 + 736 * 4;       // ~76.7KB
    const int qkv_smem  = 192 * SSTR * sizeof(__half);        // ~52.2KB
    const int proj_smem = 128 * SSTR * sizeof(__half);        // ~34.8KB
    cudaFuncSetAttribute(attn_kernel, cudaFuncAttributeMaxDynamicSharedMemorySize,
                         attn_smem);
    cudaFuncSetAttribute(qkv_mma, cudaFuncAttributeMaxDynamicSharedMemorySize,
                         qkv_smem);
    cudaFuncSetAttribute(proj_mma, cudaFuncAttributeMaxDynamicSharedMemorySize,
                         proj_smem);

    stats_kernel<<<256, 256>>>(x, skip);
    qkv_mma<<<272, 256, qkv_smem>>>(x, skip, Wq, bq, Wk, bk, Wv, bv);
    attn_kernel<<<dim3(4, 4, 8), 256, attn_smem>>>(rpb);
    proj_mma<<<256, 256, proj_smem>>>(Wo, bo, outp);
}

// round 13
// speedup vs baseline: 1.7673x; 1.7673x over previous
#include <cuda_runtime.h>
#include <cuda_fp16.h>

#define DIMC 128
#define HEADS 8
#define HD 16
#define HH 32
#define WW 32
#define ZZ 8
#define NPTS 8192   // 32*32*8
#define NXV 1024    // 16*16*4

// Scratch (device globals)
__device__ float   g_stats_x[DIMC * 2];
__device__ float   g_stats_s[DIMC * 2];
__device__ __half2 g_q16[HEADS * NXV * 8];     // [head][m][8 half2]
__device__ __half2 g_k16[HEADS * NPTS * 8];    // [head][n][8 half2]
__device__ __half2 g_v16[HEADS * NPTS * 8];    // [head][n][8 half2]
__device__ __half  g_o16[NPTS * DIMC];         // [n][j] row-major attn output
__device__ __half  g_WkT[DIMC * DIMC];         // [j][c] fp16 transposed weights
__device__ __half  g_WvT[DIMC * DIMC];
__device__ __half  g_WqT[DIMC * DIMC];
__device__ __half  g_WoT[DIMC * DIMC];         // [c][j] fp16 (Wo transposed)

// ---------------------------------------------------------------------------
// Kernel 1: instance-norm statistics (blocks 0..255) + weight transpose to
// fp16 (blocks 256..319; 64 blocks = 4 matrices x 16 tiles of 32x32).
// All four transposes are OUT[a][b] = (half)IN[b][a] on 128x128.
// ---------------------------------------------------------------------------
__global__ void stats_prep_kernel(const float* __restrict__ x,
                                  const float* __restrict__ skip,
                                  const float* __restrict__ Wq,
                                  const float* __restrict__ Wk,
                                  const float* __restrict__ Wv,
                                  const float* __restrict__ Wo) {
    __shared__ float sh1[8], sh2[8];
    __shared__ float ts[32][33];

    int b = blockIdx.x;
    if (b >= 256) {
        int t = b - 256;
        int m = t >> 4, tile = t & 15;
        int tr = (tile >> 2) * 32, tc = (tile & 3) * 32;
        const float* src = (m == 0) ? Wk : (m == 1) ? Wv : (m == 2) ? Wq : Wo;
        __half* dst = (m == 0) ? g_WkT : (m == 1) ? g_WvT : (m == 2) ? g_WqT : g_WoT;
        int lr = threadIdx.x >> 5, lc = threadIdx.x & 31;
        #pragma unroll
        for (int i = 0; i < 4; i++)
            ts[lr + i * 8][lc] = src[(tc + lr + i * 8) * DIMC + tr + lc];
        __syncthreads();
        #pragma unroll
        for (int i = 0; i < 4; i++)
            dst[(tr + lr + i * 8) * DIMC + tc + lc] = __float2half(ts[lc][lr + i * 8]);
        return;
    }

    int c = b;
    const float* src; int n; float* dst;
    if (c < DIMC) { src = x + c * NXV;              n = NXV;  dst = g_stats_x + c * 2; }
    else          { src = skip + (c - DIMC) * NPTS; n = NPTS; dst = g_stats_s + (c - DIMC) * 2; }

    float s = 0.f, s2 = 0.f;
    for (int i = threadIdx.x; i < n; i += 256) {
        float v = src[i];
        s += v; s2 += v * v;
    }
    #pragma unroll
    for (int o = 16; o; o >>= 1) {
        s  += __shfl_down_sync(0xffffffffu, s,  o);
        s2 += __shfl_down_sync(0xffffffffu, s2, o);
    }
    int wid = threadIdx.x >> 5, lid = threadIdx.x & 31;
    if (lid == 0) { sh1[wid] = s; sh2[wid] = s2; }
    __syncthreads();
    if (threadIdx.x == 0) {
        float ts2sum = 0.f, tss = 0.f;
        #pragma unroll
        for (int i = 0; i < 8; i++) { tss += sh1[i]; ts2sum += sh2[i]; }
        float mean = tss / n;
        float var  = ts2sum / n - mean * mean;
        dst[0] = mean;
        dst[1] = rsqrtf(var + 1e-5f);
    }
}

// ---- mma.sync m16n8k16 fp16 -> fp32 ---------------------------------------
__device__ __forceinline__ void mma16816(float* d, unsigned a0, unsigned a1,
                                         unsigned a2, unsigned a3,
                                         unsigned b0, unsigned b1) {
    asm volatile(
        "mma.sync.aligned.m16n8k16.row.col.f32.f16.f16.f32 "
        "{%0,%1,%2,%3},{%4,%5,%6,%7},{%8,%9},{%0,%1,%2,%3};"
        : "+f"(d[0]), "+f"(d[1]), "+f"(d[2]), "+f"(d[3])
        : "r"(a0), "r"(a1), "r"(a2), "r"(a3), "r"(b0), "r"(b1));
}

#define SSTR 136   // smem row stride (halves)

// ---------------------------------------------------------------------------
// Kernel 2: fused Q/K/V projection via tensor cores. grid 136:
//   blocks [0,64): K   [64,128): V   [128,136): Q
// One 128n x 128j x 128c tile per block. 8 warps, each 16 rows x 128 cols.
// A = normalized src transposed to smem [n][c] fp16 (from fp32 gmem);
// B = precomputed fp16 W^T [j][c] — straight vectorized copy.
// ---------------------------------------------------------------------------
__global__ __launch_bounds__(256) void qkv_mma(
        const float* __restrict__ x,  const float* __restrict__ skip,
        const float* __restrict__ bq, const float* __restrict__ bk,
        const float* __restrict__ bv) {
    extern __shared__ __half sh[];
    __half (*sA)[SSTR] = (__half(*)[SSTR])sh;             // [n 128][c 128]
    __half (*sB)[SSTR] = (__half(*)[SSTR])(sh + 128 * SSTR);

    int bid = blockIdx.x;
    const float *src, *bt, *stats;
    const __half* WT;
    __half2* outp; int strideN; float scale; int n0;
    if (bid < 64) {
        src = skip; WT = g_WkT; bt = bk; stats = g_stats_s;
        outp = g_k16; strideN = NPTS; scale = 1.f; n0 = bid * 128;
    } else if (bid < 128) {
        src = skip; WT = g_WvT; bt = bv; stats = g_stats_s;
        outp = g_v16; strideN = NPTS; scale = 1.f; n0 = (bid - 64) * 128;
    } else {
        src = x; WT = g_WqT; bt = bq; stats = g_stats_x;
        outp = g_q16; strideN = NXV; scale = 0.25f; n0 = (bid - 128) * 128;
    }
    int tid = threadIdx.x;

    // Stage A (normalize + transpose fp32 [c][n] -> fp16 [n][c])
    {
        int c = tid & 127, nh = (tid >> 7) * 64;
        float mu = stats[c * 2], rs = stats[c * 2 + 1];
        const float* sp = src + c * strideN + n0 + nh;
        #pragma unroll
        for (int i = 0; i < 16; i++) {
            float4 v = *(const float4*)(sp + i * 4);
            int n = nh + i * 4;
            sA[n + 0][c] = __float2half((v.x - mu) * rs);
            sA[n + 1][c] = __float2half((v.y - mu) * rs);
            sA[n + 2][c] = __float2half((v.z - mu) * rs);
            sA[n + 3][c] = __float2half((v.w - mu) * rs);
        }
    }
    // Stage B: vectorized fp16 copy of precomputed W^T [j][c]
    {
        int j = tid >> 1, hf = tid & 1;
        const float4* wp = (const float4*)(WT + j * DIMC + hf * 64);
        float4* dp = (float4*)&sB[j][hf * 64];
        #pragma unroll
        for (int i = 0; i < 8; i++) dp[i] = wp[i];
    }
    __syncthreads();

    int w = tid >> 5, t = tid & 31;
    int g = t >> 2, i2 = (t & 3) * 2;
    int mrow = w * 16;

    float acc[16][4];
    #pragma unroll
    for (int nt = 0; nt < 16; nt++)
        #pragma unroll
        for (int p = 0; p < 4; p++) acc[nt][p] = 0.f;

    #pragma unroll
    for (int kc = 0; kc < 8; kc++) {
        int k0 = kc * 16;
        unsigned a0 = *(const unsigned*)&sA[mrow + g][k0 + i2];
        unsigned a1 = *(const unsigned*)&sA[mrow + g + 8][k0 + i2];
        unsigned a2 = *(const unsigned*)&sA[mrow + g][k0 + i2 + 8];
        unsigned a3 = *(const unsigned*)&sA[mrow + g + 8][k0 + i2 + 8];
        #pragma unroll
        for (int nt = 0; nt < 16; nt++) {
            unsigned b0 = *(const unsigned*)&sB[nt * 8 + g][k0 + i2];
            unsigned b1 = *(const unsigned*)&sB[nt * 8 + g][k0 + i2 + 8];
            mma16816(acc[nt], a0, a1, a2, a3, b0, b1);
        }
    }

    // Epilogue: bias + scale, pack fp16 into [head][n][8 half2]
    int n1 = n0 + mrow + g;
    #pragma unroll
    for (int nt = 0; nt < 16; nt++) {
        int j = nt * 8 + i2;
        float2 bb = *(const float2*)&bt[j];
        int head = j >> 4;
        int jj = (j & 15) >> 1;
        outp[(head * strideN + n1) * 8 + jj] =
            __floats2half2_rn((acc[nt][0] + bb.x) * scale,
                              (acc[nt][1] + bb.y) * scale);
        outp[(head * strideN + n1 + 8) * 8 + jj] =
            __floats2half2_rn((acc[nt][2] + bb.x) * scale,
                              (acc[nt][3] + bb.y) * scale);
    }
}

// ---------------------------------------------------------------------------
// Kernel 3: neighborhood attention (known-good R3/R9 config).
// Tile 4(h) x 8(w) x 8(z) = 256 threads, 1 thread per point.
// Halo 8x12x8 = 768 positions of fp16 k/v in swizzled smem (~52KB).
// No-max softmax, fp32 accumulator. Output fp16 [n][head*16+d].
// grid (8 hblk, 4 wblk, 8 heads).
// ---------------------------------------------------------------------------
#define WH 12   // w halo extent
__global__ __launch_bounds__(256, 4) void attn_kernel(const float* __restrict__ rpb) {
    extern __shared__ float smem[];
    float4* sk4 = (float4*)smem;              // 1536 float4 (768 pos * 2)
    float4* sv4 = sk4 + 1536;                 // 1536 float4
    float*  sb  = (float*)(sv4 + 1536);       // 729 bias

    int head = blockIdx.z;
    int h0 = blockIdx.x * 4, w0 = blockIdx.y * 8;
    int hlo = min(max(h0 - 2, 0), HH - 5);
    int wlo = min(max(w0 - 2, 0), WW - 5);
    int tid = threadIdx.x;

    for (int i = tid; i < 729; i += 256) sb[i] = rpb[head * 729 + i];

    const float4* gk4 = (const float4*)g_k16 + head * (NPTS * 2);
    const float4* gv4 = (const float4*)g_v16 + head * (NPTS * 2);
    #pragma unroll
    for (int it = 0; it < 6; it++) {
        int idx = it * 256 + tid;             // 1536 (pos,d4) pairs
        int d4 = idx & 1, pos = idx >> 1;
        int col = pos >> 3, z1 = pos & 7;
        int wh = col / WH, wwi = col - wh * WH;
        int gh = min(hlo + wh, HH - 1);
        int gw = min(wlo + wwi, WW - 1);
        int n = gh * 256 + gw * 8 + z1;
        int s = pos * 2 + (d4 ^ (col & 1));   // XOR swizzle
        sk4[s] = gk4[n * 2 + d4];
        sv4[s] = gv4[n * 2 + d4];
    }
    __syncthreads();

    int z = tid & 7, dw = (tid >> 3) & 7, dh = tid >> 6;
    int h = h0 + dh, w = w0 + dw;
    int sh = min(max(h - 2, 0), HH - 5);
    int sw = min(max(w - 2, 0), WW - 5);
    int sz = min(max(z - 2, 0), ZZ - 5);
    int m = (h >> 1) * 64 + (w >> 1) * 4 + (z >> 1);

    __half2 q2[8];
    {
        const float4* gq4 = (const float4*)g_q16 + (head * NXV + m) * 2;
        float4 qA = gq4[0], qB = gq4[1];
        const __half2* qa = (const __half2*)&qA;
        const __half2* qb = (const __half2*)&qB;
        #pragma unroll
        for (int i = 0; i < 4; i++) { q2[i] = qa[i]; q2[4 + i] = qb[i]; }
    }

    int bh = sh - h + 4, bw = sw - w + 4, bz = sz - z + 4;

    float sum = 0.f;
    float acc[16];
    #pragma unroll
    for (int d = 0; d < 16; d++) acc[d] = 0.f;

    for (int jh = 0; jh < 5; jh++) {
        int colh = (sh + jh - hlo) * WH;
        const float* bph = sb + (bh + jh) * 81 + bz;
        for (int jw = 0; jw < 5; jw++) {
            int col = colh + (sw + jw - wlo);
            int e = col & 1;
            const float4* kp = sk4 + col * 16 + sz * 2;
            const float4* vp = sv4 + col * 16 + sz * 2;
            const float* bp = bph + (bw + jw) * 9;
            #pragma unroll
            for (int jz = 0; jz < 5; jz++) {
                float4 kA = kp[jz * 2 + e];
                float4 kB = kp[jz * 2 + 1 - e];
                const __half2* ka = (const __half2*)&kA;
                const __half2* kb = (const __half2*)&kB;
                __half2 s0 = __hmul2(q2[0], ka[0]);
                __half2 s1 = __hmul2(q2[1], ka[1]);
                s0 = __hfma2(q2[2], ka[2], s0);
                s1 = __hfma2(q2[3], ka[3], s1);
                s0 = __hfma2(q2[4], kb[0], s0);
                s1 = __hfma2(q2[5], kb[1], s1);
                s0 = __hfma2(q2[6], kb[2], s0);
                s1 = __hfma2(q2[7], kb[3], s1);
                float2 lf = __half22float2(__hadd2(s0, s1));
                float l = bp[jz] + lf.x + lf.y;
                float p = __expf(l);
                sum += p;
                float4 vA = vp[jz * 2 + e];
                float4 vB = vp[jz * 2 + 1 - e];
                const __half2* va = (const __half2*)&vA;
                const __half2* vb = (const __half2*)&vB;
                #pragma unroll
                for (int i = 0; i < 4; i++) {
                    float2 f0 = __half22float2(va[i]);
                    float2 f1 = __half22float2(vb[i]);
                    acc[2 * i]         += p * f0.x;
                    acc[2 * i + 1]     += p * f0.y;
                    acc[8 + 2 * i]     += p * f1.x;
                    acc[8 + 2 * i + 1] += p * f1.y;
                }
            }
        }
    }

    float inv = 1.f / sum;
    int n = h * 256 + w * 8 + z;
    __half2 o2[8];
    #pragma unroll
    for (int d = 0; d < 8; d++)
        o2[d] = __floats2half2_rn(acc[2 * d] * inv, acc[2 * d + 1] * inv);
    float4* dst = (float4*)(g_o16 + n * DIMC + head * 16);
    dst[0] = ((const float4*)o2)[0];
    dst[1] = ((const float4*)o2)[1];
}

// ---------------------------------------------------------------------------
// Kernel 4: output projection via tensor cores. grid 128 =
// (64 n-tiles) x (2 c-halves). Tile 128n x 64c x 128k.
// A = g_o16 [n][j] fp16 copy; B = precomputed g_WoT [c][j] fp16 copy.
// 8 warps x (16 rows x 64 cols). fp32 output [c][n] + bias.
// ---------------------------------------------------------------------------
__global__ __launch_bounds__(256) void proj_mma(
        const float* __restrict__ bo, float* __restrict__ outp) {
    extern __shared__ __half sh[];
    __half (*sA)[SSTR] = (__half(*)[SSTR])sh;                // [n 128][j 128]
    __half (*sB)[SSTR] = (__half(*)[SSTR])(sh + 128 * SSTR); // [c 64][j 128]

    int n0 = (blockIdx.x >> 1) * 128;
    int c0 = (blockIdx.x & 1) * 64;
    int tid = threadIdx.x;

    // Stage A: copy fp16 [n][j]
    {
        int n = tid & 127, jh = (tid >> 7) * 64;
        const float4* gA = (const float4*)(g_o16 + (n0 + n) * DIMC + jh);
        float4* dA = (float4*)&sA[n][jh];
        #pragma unroll
        for (int i = 0; i < 8; i++) dA[i] = gA[i];
    }
    // Stage B: copy fp16 [c][j] from precomputed WoT
    {
        int r = tid >> 2, qt = (tid & 3) * 32;
        const float4* wp = (const float4*)(g_WoT + (c0 + r) * DIMC + qt);
        float4* dp = (float4*)&sB[r][qt];
        #pragma unroll
        for (int i = 0; i < 4; i++) dp[i] = wp[i];
    }
    __syncthreads();

    int w = tid >> 5, t = tid & 31;
    int g = t >> 2, i2 = (t & 3) * 2;
    int mrow = w * 16;

    float acc[8][4];
    #pragma unroll
    for (int nt = 0; nt < 8; nt++)
        #pragma unroll
        for (int p = 0; p < 4; p++) acc[nt][p] = 0.f;

    #pragma unroll
    for (int kc = 0; kc < 8; kc++) {
        int k0 = kc * 16;
        unsigned a0 = *(const unsigned*)&sA[mrow + g][k0 + i2];
        unsigned a1 = *(const unsigned*)&sA[mrow + g + 8][k0 + i2];
        unsigned a2 = *(const unsigned*)&sA[mrow + g][k0 + i2 + 8];
        unsigned a3 = *(const unsigned*)&sA[mrow + g + 8][k0 + i2 + 8];
        #pragma unroll
        for (int nt = 0; nt < 8; nt++) {
            unsigned b0 = *(const unsigned*)&sB[nt * 8 + g][k0 + i2];
            unsigned b1 = *(const unsigned*)&sB[nt * 8 + g][k0 + i2 + 8];
            mma16816(acc[nt], a0, a1, a2, a3, b0, b1);
        }
    }

    // Epilogue: out[c][n] fp32 + bias
    int n1 = n0 + mrow + g;
    #pragma unroll
    for (int nt = 0; nt < 8; nt++) {
        int c = c0 + nt * 8 + i2;
        float2 bb = *(const float2*)&bo[c];
        outp[c * NPTS + n1]           = acc[nt][0] + bb.x;
        outp[(c + 1) * NPTS + n1]     = acc[nt][1] + bb.y;
        outp[c * NPTS + n1 + 8]       = acc[nt][2] + bb.x;
        outp[(c + 1) * NPTS + n1 + 8] = acc[nt][3] + bb.y;
    }
}

// ---------------------------------------------------------------------------
extern "C" void kernel_launch(void* const* d_in, const int* in_sizes, int n_in,
                              void* d_out, int out_size) {
    const float* x    = (const float*)d_in[0];
    const float* skip = (const float*)d_in[1];
    const float* Wq   = (const float*)d_in[2];
    const float* bq   = (const float*)d_in[3];
    const float* Wk   = (const float*)d_in[4];
    const float* bk   = (const float*)d_in[5];
    const float* Wv   = (const float*)d_in[6];
    const float* bv   = (const float*)d_in[7];
    const float* rpb  = (const float*)d_in[8];
    const float* Wo   = (const float*)d_in[9];
    const float* bo   = (const float*)d_in[10];
    float* outp = (float*)d_out;

    const int attn_smem = (1536 + 1536) * 16 + 736 * 4;       // ~52KB
    const int qkv_smem  = 256 * SSTR * sizeof(__half);        // ~69.6KB
    const int proj_smem = 192 * SSTR * sizeof(__half);        // ~52.2KB
    cudaFuncSetAttribute(attn_kernel, cudaFuncAttributeMaxDynamicSharedMemorySize,
                         attn_smem);
    cudaFuncSetAttribute(qkv_mma, cudaFuncAttributeMaxDynamicSharedMemorySize,
                         qkv_smem);
    cudaFuncSetAttribute(proj_mma, cudaFuncAttributeMaxDynamicSharedMemorySize,
                         proj_smem);

    stats_prep_kernel<<<320, 256>>>(x, skip, Wq, Wk, Wv, Wo);
    qkv_mma<<<136, 256, qkv_smem>>>(x, skip, bq, bk, bv);
    attn_kernel<<<dim3(8, 4, 8), 256, attn_smem>>>(rpb);
    proj_mma<<<128, 256, proj_smem>>>(bo, outp);
}

// round 14
// speedup vs baseline: 1.7772x; 1.0056x over previous
#include <cuda_runtime.h>
#include <cuda_fp16.h>

#define DIMC 128
#define HEADS 8
#define HD 16
#define HH 32
#define WW 32
#define ZZ 8
#define NPTS 8192   // 32*32*8
#define NXV 1024    // 16*16*4
#define LOG2E 1.44269504f

// Scratch (device globals)
__device__ float   g_stats_x[DIMC * 2];
__device__ float   g_stats_s[DIMC * 2];
__device__ __half2 g_q16[HEADS * NXV * 8];     // [head][m][8 half2]
__device__ __half2 g_k16[HEADS * NPTS * 8];    // [head][n][8 half2]
__device__ __half2 g_v16[HEADS * NPTS * 8];    // [head][n][8 half2]
__device__ __half  g_o16[NPTS * DIMC];         // [n][j] row-major attn output
__device__ __half  g_WkT[DIMC * DIMC];         // [j][c] fp16 transposed weights
__device__ __half  g_WvT[DIMC * DIMC];
__device__ __half  g_WqT[DIMC * DIMC];
__device__ __half  g_WoT[DIMC * DIMC];         // [c][j] fp16 (Wo transposed)

__device__ __forceinline__ float ex2(float x) {
    float r; asm("ex2.approx.ftz.f32 %0,%1;" : "=f"(r) : "f"(x)); return r;
}

// ---------------------------------------------------------------------------
// Kernel 1: instance-norm statistics (blocks 0..255) + weight transpose to
// fp16 (blocks 256..319).
// ---------------------------------------------------------------------------
__global__ void stats_prep_kernel(const float* __restrict__ x,
                                  const float* __restrict__ skip,
                                  const float* __restrict__ Wq,
                                  const float* __restrict__ Wk,
                                  const float* __restrict__ Wv,
                                  const float* __restrict__ Wo) {
    __shared__ float sh1[8], sh2[8];
    __shared__ float ts[32][33];

    int b = blockIdx.x;
    if (b >= 256) {
        int t = b - 256;
        int m = t >> 4, tile = t & 15;
        int tr = (tile >> 2) * 32, tc = (tile & 3) * 32;
        const float* src = (m == 0) ? Wk : (m == 1) ? Wv : (m == 2) ? Wq : Wo;
        __half* dst = (m == 0) ? g_WkT : (m == 1) ? g_WvT : (m == 2) ? g_WqT : g_WoT;
        int lr = threadIdx.x >> 5, lc = threadIdx.x & 31;
        #pragma unroll
        for (int i = 0; i < 4; i++)
            ts[lr + i * 8][lc] = src[(tc + lr + i * 8) * DIMC + tr + lc];
        __syncthreads();
        #pragma unroll
        for (int i = 0; i < 4; i++)
            dst[(tr + lr + i * 8) * DIMC + tc + lc] = __float2half(ts[lc][lr + i * 8]);
        return;
    }

    int c = b;
    const float* src; int n; float* dst;
    if (c < DIMC) { src = x + c * NXV;              n = NXV;  dst = g_stats_x + c * 2; }
    else          { src = skip + (c - DIMC) * NPTS; n = NPTS; dst = g_stats_s + (c - DIMC) * 2; }

    float s = 0.f, s2 = 0.f;
    for (int i = threadIdx.x; i < n; i += 256) {
        float v = src[i];
        s += v; s2 += v * v;
    }
    #pragma unroll
    for (int o = 16; o; o >>= 1) {
        s  += __shfl_down_sync(0xffffffffu, s,  o);
        s2 += __shfl_down_sync(0xffffffffu, s2, o);
    }
    int wid = threadIdx.x >> 5, lid = threadIdx.x & 31;
    if (lid == 0) { sh1[wid] = s; sh2[wid] = s2; }
    __syncthreads();
    if (threadIdx.x == 0) {
        float ts2sum = 0.f, tss = 0.f;
        #pragma unroll
        for (int i = 0; i < 8; i++) { tss += sh1[i]; ts2sum += sh2[i]; }
        float mean = tss / n;
        float var  = ts2sum / n - mean * mean;
        dst[0] = mean;
        dst[1] = rsqrtf(var + 1e-5f);
    }
}

// ---- mma.sync m16n8k16 fp16 -> fp32 ---------------------------------------
__device__ __forceinline__ void mma16816(float* d, unsigned a0, unsigned a1,
                                         unsigned a2, unsigned a3,
                                         unsigned b0, unsigned b1) {
    asm volatile(
        "mma.sync.aligned.m16n8k16.row.col.f32.f16.f16.f32 "
        "{%0,%1,%2,%3},{%4,%5,%6,%7},{%8,%9},{%0,%1,%2,%3};"
        : "+f"(d[0]), "+f"(d[1]), "+f"(d[2]), "+f"(d[3])
        : "r"(a0), "r"(a1), "r"(a2), "r"(a3), "r"(b0), "r"(b1));
}

#define SSTR 136   // smem row stride (halves)

// ---------------------------------------------------------------------------
// Kernel 2: fused Q/K/V projection via tensor cores. grid 136:
//   blocks [0,64): K   [64,128): V   [128,136): Q
// Q scale folds HEAD_DIM^-0.5 * log2(e) so attention can use raw ex2.
// ---------------------------------------------------------------------------
__global__ __launch_bounds__(256) void qkv_mma(
        const float* __restrict__ x,  const float* __restrict__ skip,
        const float* __restrict__ bq, const float* __restrict__ bk,
        const float* __restrict__ bv) {
    extern __shared__ __half sh[];
    __half (*sA)[SSTR] = (__half(*)[SSTR])sh;             // [n 128][c 128]
    __half (*sB)[SSTR] = (__half(*)[SSTR])(sh + 128 * SSTR);

    int bid = blockIdx.x;
    const float *src, *bt, *stats;
    const __half* WT;
    __half2* outp; int strideN; float scale; int n0;
    if (bid < 64) {
        src = skip; WT = g_WkT; bt = bk; stats = g_stats_s;
        outp = g_k16; strideN = NPTS; scale = 1.f; n0 = bid * 128;
    } else if (bid < 128) {
        src = skip; WT = g_WvT; bt = bv; stats = g_stats_s;
        outp = g_v16; strideN = NPTS; scale = 1.f; n0 = (bid - 64) * 128;
    } else {
        src = x; WT = g_WqT; bt = bq; stats = g_stats_x;
        outp = g_q16; strideN = NXV; scale = 0.25f * LOG2E; n0 = (bid - 128) * 128;
    }
    int tid = threadIdx.x;

    // Stage A (normalize + transpose fp32 [c][n] -> fp16 [n][c])
    {
        int c = tid & 127, nh = (tid >> 7) * 64;
        float mu = stats[c * 2], rs = stats[c * 2 + 1];
        const float* sp = src + c * strideN + n0 + nh;
        #pragma unroll
        for (int i = 0; i < 16; i++) {
            float4 v = *(const float4*)(sp + i * 4);
            int n = nh + i * 4;
            sA[n + 0][c] = __float2half((v.x - mu) * rs);
            sA[n + 1][c] = __float2half((v.y - mu) * rs);
            sA[n + 2][c] = __float2half((v.z - mu) * rs);
            sA[n + 3][c] = __float2half((v.w - mu) * rs);
        }
    }
    // Stage B: vectorized fp16 copy of precomputed W^T [j][c]
    {
        int j = tid >> 1, hf = tid & 1;
        const float4* wp = (const float4*)(WT + j * DIMC + hf * 64);
        float4* dp = (float4*)&sB[j][hf * 64];
        #pragma unroll
        for (int i = 0; i < 8; i++) dp[i] = wp[i];
    }
    __syncthreads();

    int w = tid >> 5, t = tid & 31;
    int g = t >> 2, i2 = (t & 3) * 2;
    int mrow = w * 16;

    float acc[16][4];
    #pragma unroll
    for (int nt = 0; nt < 16; nt++)
        #pragma unroll
        for (int p = 0; p < 4; p++) acc[nt][p] = 0.f;

    #pragma unroll
    for (int kc = 0; kc < 8; kc++) {
        int k0 = kc * 16;
        unsigned a0 = *(const unsigned*)&sA[mrow + g][k0 + i2];
        unsigned a1 = *(const unsigned*)&sA[mrow + g + 8][k0 + i2];
        unsigned a2 = *(const unsigned*)&sA[mrow + g][k0 + i2 + 8];
        unsigned a3 = *(const unsigned*)&sA[mrow + g + 8][k0 + i2 + 8];
        #pragma unroll
        for (int nt = 0; nt < 16; nt++) {
            unsigned b0 = *(const unsigned*)&sB[nt * 8 + g][k0 + i2];
            unsigned b1 = *(const unsigned*)&sB[nt * 8 + g][k0 + i2 + 8];
            mma16816(acc[nt], a0, a1, a2, a3, b0, b1);
        }
    }

    // Epilogue: bias + scale, pack fp16 into [head][n][8 half2]
    int n1 = n0 + mrow + g;
    #pragma unroll
    for (int nt = 0; nt < 16; nt++) {
        int j = nt * 8 + i2;
        float2 bb = *(const float2*)&bt[j];
        int head = j >> 4;
        int jj = (j & 15) >> 1;
        outp[(head * strideN + n1) * 8 + jj] =
            __floats2half2_rn((acc[nt][0] + bb.x) * scale,
                              (acc[nt][1] + bb.y) * scale);
        outp[(head * strideN + n1 + 8) * 8 + jj] =
            __floats2half2_rn((acc[nt][2] + bb.x) * scale,
                              (acc[nt][3] + bb.y) * scale);
    }
}

// ---------------------------------------------------------------------------
// Kernel 3: neighborhood attention. SAME per-thread inner loop as the proven
// R3/R9 kernel; only the block shape changes to raise occupancy:
// tile 4(h) x 4(w) x 8(z) = 128 pts, 128 threads, halo 8x8x8 = 512 pos,
// smem ~35KB -> ~3.5 resident blocks/SM in one wave (grid 8x8x8 = 512).
// Logits are pre-scaled by log2(e) (q and bias), so p = ex2(l).
// ---------------------------------------------------------------------------
__global__ __launch_bounds__(128, 6) void attn_kernel(const float* __restrict__ rpb) {
    extern __shared__ float smem[];
    float4* sk4 = (float4*)smem;              // 1024 float4 (512 pos * 2)
    float4* sv4 = sk4 + 1024;                 // 1024 float4
    float*  sb  = (float*)(sv4 + 1024);       // 729 bias

    int head = blockIdx.z;
    int h0 = blockIdx.x * 4, w0 = blockIdx.y * 4;
    int hlo = min(max(h0 - 2, 0), HH - 5);
    int wlo = min(max(w0 - 2, 0), WW - 5);
    int tid = threadIdx.x;

    for (int i = tid; i < 729; i += 128) sb[i] = rpb[head * 729 + i] * LOG2E;

    const float4* gk4 = (const float4*)g_k16 + head * (NPTS * 2);
    const float4* gv4 = (const float4*)g_v16 + head * (NPTS * 2);
    #pragma unroll
    for (int it = 0; it < 8; it++) {
        int idx = it * 128 + tid;             // 1024 (pos,d4) pairs
        int d4 = idx & 1, pos = idx >> 1;
        int col = pos >> 3, z1 = pos & 7;
        int wwi = col & 7, wh = col >> 3;
        int gh = min(hlo + wh, HH - 1);
        int gw = min(wlo + wwi, WW - 1);
        int n = gh * 256 + gw * 8 + z1;
        int s = pos * 2 + (d4 ^ (col & 1));   // XOR swizzle
        sk4[s] = gk4[n * 2 + d4];
        sv4[s] = gv4[n * 2 + d4];
    }
    __syncthreads();

    int z = tid & 7, dw = (tid >> 3) & 3, dh = tid >> 5;
    int h = h0 + dh, w = w0 + dw;
    int sh = min(max(h - 2, 0), HH - 5);
    int sw = min(max(w - 2, 0), WW - 5);
    int sz = min(max(z - 2, 0), ZZ - 5);
    int m = (h >> 1) * 64 + (w >> 1) * 4 + (z >> 1);

    __half2 q2[8];
    {
        const float4* gq4 = (const float4*)g_q16 + (head * NXV + m) * 2;
        float4 qA = gq4[0], qB = gq4[1];
        const __half2* qa = (const __half2*)&qA;
        const __half2* qb = (const __half2*)&qB;
        #pragma unroll
        for (int i = 0; i < 4; i++) { q2[i] = qa[i]; q2[4 + i] = qb[i]; }
    }

    int bh = sh - h + 4, bw = sw - w + 4, bz = sz - z + 4;

    float sum = 0.f;
    float acc[16];
    #pragma unroll
    for (int d = 0; d < 16; d++) acc[d] = 0.f;

    for (int jh = 0; jh < 5; jh++) {
        int colh = (sh + jh - hlo) * 8;
        const float* bph = sb + (bh + jh) * 81 + bz;
        for (int jw = 0; jw < 5; jw++) {
            int col = colh + (sw + jw - wlo);
            int e = col & 1;
            const float4* kp = sk4 + col * 16 + sz * 2;
            const float4* vp = sv4 + col * 16 + sz * 2;
            const float* bp = bph + (bw + jw) * 9;
            #pragma unroll
            for (int jz = 0; jz < 5; jz++) {
                float4 kA = kp[jz * 2 + e];
                float4 kB = kp[jz * 2 + 1 - e];
                const __half2* ka = (const __half2*)&kA;
                const __half2* kb = (const __half2*)&kB;
                __half2 s0 = __hmul2(q2[0], ka[0]);
                __half2 s1 = __hmul2(q2[1], ka[1]);
                s0 = __hfma2(q2[2], ka[2], s0);
                s1 = __hfma2(q2[3], ka[3], s1);
                s0 = __hfma2(q2[4], kb[0], s0);
                s1 = __hfma2(q2[5], kb[1], s1);
                s0 = __hfma2(q2[6], kb[2], s0);
                s1 = __hfma2(q2[7], kb[3], s1);
                float2 lf = __half22float2(__hadd2(s0, s1));
                float l = bp[jz] + lf.x + lf.y;
                float p = ex2(l);
                sum += p;
                float4 vA = vp[jz * 2 + e];
                float4 vB = vp[jz * 2 + 1 - e];
                const __half2* va = (const __half2*)&vA;
                const __half2* vb = (const __half2*)&vB;
                #pragma unroll
                for (int i = 0; i < 4; i++) {
                    float2 f0 = __half22float2(va[i]);
                    float2 f1 = __half22float2(vb[i]);
                    acc[2 * i]         += p * f0.x;
                    acc[2 * i + 1]     += p * f0.y;
                    acc[8 + 2 * i]     += p * f1.x;
                    acc[8 + 2 * i + 1] += p * f1.y;
                }
            }
        }
    }

    float inv = 1.f / sum;
    int n = h * 256 + w * 8 + z;
    __half2 o2[8];
    #pragma unroll
    for (int d = 0; d < 8; d++)
        o2[d] = __floats2half2_rn(acc[2 * d] * inv, acc[2 * d + 1] * inv);
    float4* dst = (float4*)(g_o16 + n * DIMC + head * 16);
    dst[0] = ((const float4*)o2)[0];
    dst[1] = ((const float4*)o2)[1];
}

// ---------------------------------------------------------------------------
// Kernel 4: output projection via tensor cores. grid 128 =
// (64 n-tiles) x (2 c-halves). Tile 128n x 64c x 128k.
// ---------------------------------------------------------------------------
__global__ __launch_bounds__(256) void proj_mma(
        const float* __restrict__ bo, float* __restrict__ outp) {
    extern __shared__ __half sh[];
    __half (*sA)[SSTR] = (__half(*)[SSTR])sh;                // [n 128][j 128]
    __half (*sB)[SSTR] = (__half(*)[SSTR])(sh + 128 * SSTR); // [c 64][j 128]

    int n0 = (blockIdx.x >> 1) * 128;
    int c0 = (blockIdx.x & 1) * 64;
    int tid = threadIdx.x;

    // Stage A: copy fp16 [n][j]
    {
        int n = tid & 127, jh = (tid >> 7) * 64;
        const float4* gA = (const float4*)(g_o16 + (n0 + n) * DIMC + jh);
        float4* dA = (float4*)&sA[n][jh];
        #pragma unroll
        for (int i = 0; i < 8; i++) dA[i] = gA[i];
    }
    // Stage B: copy fp16 [c][j] from precomputed WoT
    {
        int r = tid >> 2, qt = (tid & 3) * 32;
        const float4* wp = (const float4*)(g_WoT + (c0 + r) * DIMC + qt);
        float4* dp = (float4*)&sB[r][qt];
        #pragma unroll
        for (int i = 0; i < 4; i++) dp[i] = wp[i];
    }
    __syncthreads();

    int w = tid >> 5, t = tid & 31;
    int g = t >> 2, i2 = (t & 3) * 2;
    int mrow = w * 16;

    float acc[8][4];
    #pragma unroll
    for (int nt = 0; nt < 8; nt++)
        #pragma unroll
        for (int p = 0; p < 4; p++) acc[nt][p] = 0.f;

    #pragma unroll
    for (int kc = 0; kc < 8; kc++) {
        int k0 = kc * 16;
        unsigned a0 = *(const unsigned*)&sA[mrow + g][k0 + i2];
        unsigned a1 = *(const unsigned*)&sA[mrow + g + 8][k0 + i2];
        unsigned a2 = *(const unsigned*)&sA[mrow + g][k0 + i2 + 8];
        unsigned a3 = *(const unsigned*)&sA[mrow + g + 8][k0 + i2 + 8];
        #pragma unroll
        for (int nt = 0; nt < 8; nt++) {
            unsigned b0 = *(const unsigned*)&sB[nt * 8 + g][k0 + i2];
            unsigned b1 = *(const unsigned*)&sB[nt * 8 + g][k0 + i2 + 8];
            mma16816(acc[nt], a0, a1, a2, a3, b0, b1);
        }
    }

    // Epilogue: out[c][n] fp32 + bias
    int n1 = n0 + mrow + g;
    #pragma unroll
    for (int nt = 0; nt < 8; nt++) {
        int c = c0 + nt * 8 + i2;
        float2 bb = *(const float2*)&bo[c];
        outp[c * NPTS + n1]           = acc[nt][0] + bb.x;
        outp[(c + 1) * NPTS + n1]     = acc[nt][1] + bb.y;
        outp[c * NPTS + n1 + 8]       = acc[nt][2] + bb.x;
        outp[(c + 1) * NPTS + n1 + 8] = acc[nt][3] + bb.y;
    }
}

// ---------------------------------------------------------------------------
extern "C" void kernel_launch(void* const* d_in, const int* in_sizes, int n_in,
                              void* d_out, int out_size) {
    const float* x    = (const float*)d_in[0];
    const float* skip = (const float*)d_in[1];
    const float* Wq   = (const float*)d_in[2];
    const float* bq   = (const float*)d_in[3];
    const float* Wk   = (const float*)d_in[4];
    const float* bk   = (const float*)d_in[5];
    const float* Wv   = (const float*)d_in[6];
    const float* bv   = (const float*)d_in[7];
    const float* rpb  = (const float*)d_in[8];
    const float* Wo   = (const float*)d_in[9];
    const float* bo   = (const float*)d_in[10];
    float* outp = (float*)d_out;

    const int attn_smem = (1024 + 1024) * 16 + 736 * 4;       // ~35.7KB
    const int qkv_smem  = 256 * SSTR * sizeof(__half);        // ~69.6KB
    const int proj_smem = 192 * SSTR * sizeof(__half);        // ~52.2KB
    cudaFuncSetAttribute(attn_kernel, cudaFuncAttributeMaxDynamicSharedMemorySize,
                         attn_smem);
    cudaFuncSetAttribute(qkv_mma, cudaFuncAttributeMaxDynamicSharedMemorySize,
                         qkv_smem);
    cudaFuncSetAttribute(proj_mma, cudaFuncAttributeMaxDynamicSharedMemorySize,
                         proj_smem);

    stats_prep_kernel<<<320, 256>>>(x, skip, Wq, Wk, Wv, Wo);
    qkv_mma<<<136, 256, qkv_smem>>>(x, skip, bq, bk, bv);
    attn_kernel<<<dim3(8, 8, 8), 128, attn_smem>>>(rpb);
    proj_mma<<<128, 256, proj_smem>>>(bo, outp);
}